// round 16
// baseline (speedup 1.0000x reference)
#include <cuda_runtime.h>
#include <cuda_fp16.h>
#include <cstdint>
#include <math.h>

// Problem constants
#define BB    4
#define NQ    64
#define NCTX  1024
#define DIMV  768
#define NHD   8
#define DH    96
#define RNK   64
#define QR    4096      // NQ*RNK

// Scratch (static device arrays — no allocation allowed)
__device__ float g_q    [BB*NQ*DIMV];
__device__ float g_k    [BB*NCTX*DIMV];
__device__ float g_attn [BB*NHD*NQ*NCTX];
__device__ float g_acc  [BB*NQ*NHD*RNK];
__device__ float g_stats[BB*NCTX*2];          // per-row LN mean/rstd
// fp16 operands / intermediates
__device__ __half g_h1h  [BB*NCTX*QR];        // h1 stored fp16 (33.5MB)
__device__ __half g_ctx16 [BB*NCTX*DIMV];
__device__ __half g_x16   [BB*NQ*DIMV];
__device__ __half g_pre16 [BB*NQ*DIMV];
__device__ __half g_wv1t16[QR*DIMV];          // Wv1^T [N=4096, K=768]
__device__ __half g_wkt16 [DIMV*DIMV];        // Wk^T  [768, 768]
__device__ __half g_wqt16 [DIMV*DIMV];        // Wq^T
__device__ __half g_woutt16[DIMV*DIMV];       // Wout^T

// ===========================================================================
// PTX helpers (baseline PTX only — harness targets compute_103, no 'a' feats)
// ===========================================================================
__device__ __forceinline__ uint32_t smem_u32(const void* p) {
    uint32_t a;
    asm("{ .reg .u64 t; cvta.to.shared.u64 t, %1; cvt.u32.u64 %0, t; }"
        : "=r"(a) : "l"(p));
    return a;
}
__device__ __forceinline__ void cp16(uint32_t dst, const void* src) {
    asm volatile("cp.async.cg.shared.global [%0], [%1], 16;" :: "r"(dst), "l"(src));
}
__device__ __forceinline__ void ldm_x4(uint32_t* r, uint32_t addr) {
    asm volatile("ldmatrix.sync.aligned.m8n8.x4.shared.b16 {%0,%1,%2,%3}, [%4];"
                 : "=r"(r[0]), "=r"(r[1]), "=r"(r[2]), "=r"(r[3]) : "r"(addr));
}
__device__ __forceinline__ void mma16816h(float* c, const uint32_t* a, const uint32_t* b) {
    asm volatile(
        "mma.sync.aligned.m16n8k16.row.col.f32.f16.f16.f32 "
        "{%0,%1,%2,%3}, {%4,%5,%6,%7}, {%8,%9}, {%0,%1,%2,%3};"
        : "+f"(c[0]), "+f"(c[1]), "+f"(c[2]), "+f"(c[3])
        : "r"(a[0]), "r"(a[1]), "r"(a[2]), "r"(a[3]), "r"(b[0]), "r"(b[1]));
}
__device__ __forceinline__ void store2(float* p, float a, float b) {
    *(float2*)p = make_float2(a, b);
}
__device__ __forceinline__ void store2(__half* p, float a, float b) {
    *(__half2*)p = __floats2half2_rn(a, b);
}

// ===========================================================================
// Single-pass fp16 GEMM via mma.sync: C[M,N] = A[M,K] @ B^T, B in [N,K].
// OutT = float or __half. CTA tile 128x128, 8 warps (4Mw x 2Nw), K-chunk 64,
// 4-stage cp.async pipeline, XOR-swizzled SMEM.
// ===========================================================================
#define STAGE_BYTES 32768
template <typename OutT>
__global__ __launch_bounds__(256, 1)
void mma_gemm(const __half* __restrict__ A16, const __half* __restrict__ B16,
              OutT* __restrict__ C, int M, int N, int K) {
    extern __shared__ char smem_raw[];
    const uint32_t sb0 = smem_u32(smem_raw);
    const uint32_t sbase = (sb0 + 1023u) & ~1023u;     // 1KB-aligned tile area
    const int tid  = threadIdx.x;
    const int wid  = tid >> 5, lane = tid & 31;
    const int mw   = wid & 3, nw = wid >> 2;           // warp grid 4x2
    const int bm = blockIdx.y * 128, bn = blockIdx.x * 128;

    const __half* gsrc[2] = { A16 + (size_t)bm * K, B16 + (size_t)bn * K };

    const int ldrow = tid >> 3;           // 0..31  (x4 row groups of 32)
    const int ldq   = tid & 7;            // 16B column within 128B row
    uint32_t sdst[4];
    #pragma unroll
    for (int u = 0; u < 4; ++u) {
        uint32_t off = (uint32_t)((ldrow + u * 32) * 128 + ldq * 16);
        sdst[u] = off ^ ((off >> 3) & 0x70u);
    }

    auto issue_chunk = [&](int cc, uint32_t stb) {
        const int kc = cc << 6;
        #pragma unroll
        for (int a = 0; a < 2; ++a) {
            const __half* s = gsrc[a] + kc + ldq * 8;
            #pragma unroll
            for (int u = 0; u < 4; ++u)
                cp16(stb + a * 16384 + sdst[u], s + (size_t)(ldrow + u * 32) * K);
        }
    };

    uint32_t aOff[2], aPerm[2];
    #pragma unroll
    for (int mt = 0; mt < 2; ++mt) {
        int row = mw * 32 + mt * 16 + (lane & 15);
        aOff[mt]  = (uint32_t)(row * 128 + (lane >> 4) * 16);
        aPerm[mt] = (uint32_t)((row & 7) << 4);
    }
    const int nlb = nw * 64 + (lane & 7) + ((lane >> 4) << 3);
    const uint32_t bOff0 = (uint32_t)(nlb * 128 + ((lane >> 3) & 1) * 16);
    const uint32_t bPerm = (uint32_t)((nlb & 7) << 4);

    float acc[2][8][4];
    #pragma unroll
    for (int mt = 0; mt < 2; ++mt)
        #pragma unroll
        for (int nt = 0; nt < 8; ++nt)
            #pragma unroll
            for (int j = 0; j < 4; ++j) acc[mt][nt][j] = 0.f;

    const int nchunks = K >> 6;

    issue_chunk(0, sbase);
    asm volatile("cp.async.commit_group;");
    issue_chunk(1, sbase + STAGE_BYTES);
    asm volatile("cp.async.commit_group;");
    issue_chunk(2, sbase + 2 * STAGE_BYTES);
    asm volatile("cp.async.commit_group;");

    for (int c = 0; c < nchunks; ++c) {
        if (c + 3 < nchunks) {
            issue_chunk(c + 3, sbase + (uint32_t)((c + 3) & 3) * STAGE_BYTES);
            asm volatile("cp.async.commit_group;");
            asm volatile("cp.async.wait_group 3;");
        } else if (c + 2 < nchunks) {
            asm volatile("cp.async.wait_group 2;");
        } else if (c + 1 < nchunks) {
            asm volatile("cp.async.wait_group 1;");
        } else {
            asm volatile("cp.async.wait_group 0;");
        }
        __syncthreads();

        const uint32_t stb = sbase + (uint32_t)(c & 3) * STAGE_BYTES;
        const uint32_t aB = stb, bB = stb + 16384;

        #pragma unroll
        for (int ks = 0; ks < 4; ++ks) {
            const uint32_t k32 = (uint32_t)(ks * 32);
            uint32_t a16[2][4];
            #pragma unroll
            for (int mt = 0; mt < 2; ++mt)
                ldm_x4(a16[mt], aB + ((aOff[mt] + k32) ^ aPerm[mt]));
            #pragma unroll
            for (int np = 0; np < 4; ++np) {
                uint32_t bfr[4];
                const uint32_t bo = bOff0 + (uint32_t)(np * 2048) + k32;
                ldm_x4(bfr, bB + (bo ^ bPerm));
                #pragma unroll
                for (int mt = 0; mt < 2; ++mt) {
                    mma16816h(acc[mt][np * 2],     a16[mt], bfr);
                    mma16816h(acc[mt][np * 2 + 1], a16[mt], bfr + 2);
                }
            }
        }
        __syncthreads();
    }

    const int r0 = bm + mw * 32 + (lane >> 2);
    const int c0 = bn + nw * 64 + (lane & 3) * 2;
    #pragma unroll
    for (int mt = 0; mt < 2; ++mt) {
        #pragma unroll
        for (int nt = 0; nt < 8; ++nt) {
            OutT* p0 = C + (size_t)(r0 + mt * 16) * N + c0 + nt * 8;
            OutT* p1 = p0 + (size_t)8 * N;
            store2(p0, acc[mt][nt][0], acc[mt][nt][1]);
            store2(p1, acc[mt][nt][2], acc[mt][nt][3]);
        }
    }
}

// ===========================================================================
// fp32 -> fp16 (same layout)
// ===========================================================================
__global__ __launch_bounds__(256) void cvt_f16(const float* __restrict__ x,
                                               __half* __restrict__ y, int n4) {
    int i = blockIdx.x * 256 + threadIdx.x;
    if (i >= n4) return;
    float4 v = ((const float4*)x)[i];
    ((__half2*)y)[i * 2]     = __floats2half2_rn(v.x, v.y);
    ((__half2*)y)[i * 2 + 1] = __floats2half2_rn(v.z, v.w);
}

// W[K,N] fp32 -> W^T fp16 [N,K]
__global__ void cvt_t_f16(const float* __restrict__ W,
                          __half* __restrict__ T, int K, int N) {
    __shared__ float t[32][33];
    const int n0 = blockIdx.x * 32, k0 = blockIdx.y * 32;
    const int tx = threadIdx.x, ty = threadIdx.y;   // 32 x 8
    #pragma unroll
    for (int u = 0; u < 4; ++u) {
        int r = ty + u * 8;
        t[r][tx] = W[(size_t)(k0 + r) * N + n0 + tx];
    }
    __syncthreads();
    #pragma unroll
    for (int u = 0; u < 4; ++u) {
        int r = ty + u * 8;               // local n
        T[(size_t)(n0 + r) * K + k0 + tx] = __float2half_rn(t[tx][r]);
    }
}

// ===========================================================================
// LN statistics from fp16 h1: per row (4096 wide) -> (mean, rstd)
// ===========================================================================
__global__ __launch_bounds__(256) void ln_stats(const __half* __restrict__ h1,
                                                float* __restrict__ stats) {
    __shared__ float r1[8], r2[8];
    const int row = blockIdx.x;
    const __half* p = h1 + (size_t)row * QR;
    const int tid = threadIdx.x, lane = tid & 31, wid = tid >> 5;

    float s = 0.f, ss = 0.f;
    #pragma unroll
    for (int u = 0; u < 2; ++u) {
        uint4 uu = *(const uint4*)(p + tid * 16 + u * 8);
        const uint32_t w[4] = {uu.x, uu.y, uu.z, uu.w};
        #pragma unroll
        for (int j = 0; j < 4; ++j) {
            float2 f = __half22float2(*(const __half2*)&w[j]);
            s  += f.x + f.y;
            ss += f.x * f.x + f.y * f.y;
        }
    }
    #pragma unroll
    for (int o = 16; o; o >>= 1) {
        s  += __shfl_xor_sync(0xffffffffu, s, o);
        ss += __shfl_xor_sync(0xffffffffu, ss, o);
    }
    if (lane == 0) { r1[wid] = s; r2[wid] = ss; }
    __syncthreads();
    if (tid == 0) {
        s = 0.f; ss = 0.f;
        #pragma unroll
        for (int w = 0; w < 8; ++w) { s += r1[w]; ss += r2[w]; }
        const float mean = s * (1.f / 4096.f);
        const float var  = ss * (1.f / 4096.f) - mean * mean;
        stats[row * 2]     = mean;
        stats[row * 2 + 1] = rsqrtf(var + 1e-5f);
    }
}

// ===========================================================================
// sim[b,h,i,j] = (1/sqrt(dh)) * q[b,i,h*96:] . k[b,j,h*96:]
// ===========================================================================
__global__ __launch_bounds__(256) void sim_kernel(const float* __restrict__ q,
                                                  const float* __restrict__ k,
                                                  float* __restrict__ attn) {
    __shared__ float Qs[96][64];
    __shared__ float Ks[32][128];
    const int bh = blockIdx.y;
    const int b = bh >> 3, h = bh & 7;
    const int j0 = blockIdx.x * 128;
    const int tid = threadIdx.x;

    #pragma unroll
    for (int u = 0; u < 6; ++u) {
        int lin = tid + u * 256;
        int i = lin / 24, c4 = lin % 24;
        float4 v = *(const float4*)(q + (size_t)(b * NQ + i) * DIMV + h * DH + c4 * 4);
        Qs[c4 * 4 + 0][i] = v.x;
        Qs[c4 * 4 + 1][i] = v.y;
        Qs[c4 * 4 + 2][i] = v.z;
        Qs[c4 * 4 + 3][i] = v.w;
    }

    const int tx = tid & 15, ty = tid >> 4;
    float acc[4][8] = {};

    for (int kc = 0; kc < 96; kc += 32) {
        __syncthreads();
        #pragma unroll
        for (int u = 0; u < 4; ++u) {
            int lin = tid + u * 256;
            int j = lin >> 3, c4 = lin & 7;
            float4 v = *(const float4*)(k + (size_t)(b * NCTX + j0 + j) * DIMV + h * DH + kc + c4 * 4);
            Ks[c4 * 4 + 0][j] = v.x;
            Ks[c4 * 4 + 1][j] = v.y;
            Ks[c4 * 4 + 2][j] = v.z;
            Ks[c4 * 4 + 3][j] = v.w;
        }
        __syncthreads();
        #pragma unroll
        for (int kk = 0; kk < 32; ++kk) {
            float4 a = *(float4*)&Qs[kc + kk][ty * 4];
            float4 b0 = *(float4*)&Ks[kk][tx * 8];
            float4 b1 = *(float4*)&Ks[kk][tx * 8 + 4];
            float af[4] = {a.x, a.y, a.z, a.w};
            float bf[8] = {b0.x, b0.y, b0.z, b0.w, b1.x, b1.y, b1.z, b1.w};
            #pragma unroll
            for (int i = 0; i < 4; ++i)
                #pragma unroll
                for (int j = 0; j < 8; ++j)
                    acc[i][j] += af[i] * bf[j];
        }
    }

    const float scale = 0.10206207261596576f;  // 1/sqrt(96)
    #pragma unroll
    for (int i = 0; i < 4; ++i) {
        size_t base = (size_t)((b * NHD + h) * NQ + ty * 4 + i) * NCTX + j0 + tx * 8;
        float4 o0 = {acc[i][0] * scale, acc[i][1] * scale, acc[i][2] * scale, acc[i][3] * scale};
        float4 o1 = {acc[i][4] * scale, acc[i][5] * scale, acc[i][6] * scale, acc[i][7] * scale};
        *(float4*)(attn + base) = o0;
        *(float4*)(attn + base + 4) = o1;
    }
}

// ===========================================================================
// Softmax over last dim (1024) of attn, in place.
// ===========================================================================
__global__ __launch_bounds__(256) void softmax_kernel(float* __restrict__ attn) {
    __shared__ float red[8];
    const int row = blockIdx.x;
    float* p = attn + (size_t)row * NCTX;
    const int tid = threadIdx.x, lane = tid & 31, wid = tid >> 5;

    float4 v = *(float4*)(p + tid * 4);
    float m = fmaxf(fmaxf(v.x, v.y), fmaxf(v.z, v.w));
    #pragma unroll
    for (int o = 16; o; o >>= 1) m = fmaxf(m, __shfl_xor_sync(0xffffffffu, m, o));
    if (lane == 0) red[wid] = m;
    __syncthreads();
    m = red[0];
    #pragma unroll
    for (int w = 1; w < 8; ++w) m = fmaxf(m, red[w]);

    v.x = __expf(v.x - m);
    v.y = __expf(v.y - m);
    v.z = __expf(v.z - m);
    v.w = __expf(v.w - m);
    float s = v.x + v.y + v.z + v.w;
    #pragma unroll
    for (int o = 16; o; o >>= 1) s += __shfl_xor_sync(0xffffffffu, s, o);
    __syncthreads();
    if (lane == 0) red[wid] = s;
    __syncthreads();
    s = 0.f;
    #pragma unroll
    for (int w = 0; w < 8; ++w) s += red[w];
    const float inv = 1.f / s;
    v.x *= inv; v.y *= inv; v.z *= inv; v.w *= inv;
    *(float4*)(p + tid * 4) = v;
}

// ===========================================================================
// acc[b,i,h,r] = sum_j attn[b,h,i,j] * LN(h1)[b,j,i*64+r]   (LN fused, fp16 h1)
// ===========================================================================
__global__ __launch_bounds__(256) void accred_kernel(const float* __restrict__ attn,
                                                     const __half* __restrict__ h1,
                                                     const float* __restrict__ stats,
                                                     const float* __restrict__ ln_g,
                                                     const float* __restrict__ ln_b,
                                                     float* __restrict__ accb) {
    __shared__ float vs[64][64];
    __shared__ float as_[8][64];
    __shared__ float gsh[64], bsh[64];
    const int bi = blockIdx.x;
    const int b = bi >> 6, i = bi & 63;
    const int tid = threadIdx.x;
    const int h = tid >> 5, lane = tid & 31;

    if (tid < 64) {
        gsh[tid] = ln_g[i * RNK + tid];
        bsh[tid] = ln_b[i * RNK + tid];
    }

    float acc0 = 0.f, acc1 = 0.f;

    for (int jt = 0; jt < NCTX; jt += 64) {
        __syncthreads();
        {
            int e = tid * 2;
            int he = e >> 6, je = e & 63;
            float2 v = *(const float2*)(attn + (size_t)((b * NHD + he) * NQ + i) * NCTX + jt + je);
            as_[he][je] = v.x;
            as_[he][je + 1] = v.y;
        }
        {
            int rrow = tid >> 2;
            int cbase = (tid & 3) * 16;
            const int grow = b * NCTX + jt + rrow;
            const float2 st = *(const float2*)(stats + grow * 2);
            const float mu = st.x, rs = st.y;
            const __half* src = h1 + (size_t)grow * QR + i * RNK + cbase;
            #pragma unroll
            for (int u = 0; u < 2; ++u) {
                uint4 uu = *(const uint4*)(src + u * 8);
                const uint32_t w[4] = {uu.x, uu.y, uu.z, uu.w};
                #pragma unroll
                for (int j = 0; j < 4; ++j) {
                    float2 f = __half22float2(*(const __half2*)&w[j]);
                    const int cb = cbase + u * 8 + j * 2;
                    vs[rrow][cb]     = (f.x - mu) * rs * gsh[cb]     + bsh[cb];
                    vs[rrow][cb + 1] = (f.y - mu) * rs * gsh[cb + 1] + bsh[cb + 1];
                }
            }
        }
        __syncthreads();
        #pragma unroll 8
        for (int j = 0; j < 64; ++j) {
            float a = as_[h][j];
            acc0 += a * vs[j][lane];
            acc1 += a * vs[j][lane + 32];
        }
    }
    size_t base = (size_t)((b * NQ + i) * NHD + h) * RNK;
    accb[base + lane] = acc0;
    accb[base + lane + 32] = acc1;
}

// ===========================================================================
// pre16[b,i,d] = sum_r acc[b,i,h(d),r] * Wc[i,r,d]   (fp16 output)
// ===========================================================================
__global__ __launch_bounds__(256) void mix_kernel(const float* __restrict__ accb,
                                                  const float* __restrict__ Wc,
                                                  __half* __restrict__ pre) {
    __shared__ float as_[8][64];
    const int bi = blockIdx.x;
    const int b = bi >> 6, i = bi & 63;
    const int tid = threadIdx.x;

    ((float2*)&as_[0][0])[tid] = ((const float2*)(accb + (size_t)(b * NQ + i) * NHD * RNK))[tid];
    __syncthreads();

    #pragma unroll
    for (int u = 0; u < 3; ++u) {
        const int d = tid + u * 256;
        const int h = d / DH;
        const float* w = Wc + (size_t)i * RNK * DIMV + d;
        float s = 0.f;
        #pragma unroll 8
        for (int r = 0; r < 64; ++r) s += as_[h][r] * w[(size_t)r * DIMV];
        pre[(size_t)(b * NQ + i) * DIMV + d] = __float2half_rn(s);
    }
}

// ===========================================================================
// Launch
// ===========================================================================
extern "C" void kernel_launch(void* const* d_in, const int* in_sizes, int n_in,
                              void* d_out, int out_size) {
    const float* x    = (const float*)d_in[0];
    const float* ctx  = (const float*)d_in[1];
    const float* Wq   = (const float*)d_in[2];
    const float* Wk   = (const float*)d_in[3];
    const float* Wv1  = (const float*)d_in[4];
    const float* ln_g = (const float*)d_in[5];
    const float* ln_b = (const float*)d_in[6];
    const float* Wc   = (const float*)d_in[7];
    const float* Wout = (const float*)d_in[8];
    float* out = (float*)d_out;

    float *q, *k, *attn, *acc, *stats;
    __half *h1h, *c16, *x16, *pre16, *v1t16, *wkt16, *wqt16, *wot16;
    cudaGetSymbolAddress((void**)&q,     g_q);
    cudaGetSymbolAddress((void**)&k,     g_k);
    cudaGetSymbolAddress((void**)&attn,  g_attn);
    cudaGetSymbolAddress((void**)&acc,   g_acc);
    cudaGetSymbolAddress((void**)&stats, g_stats);
    cudaGetSymbolAddress((void**)&h1h,   g_h1h);
    cudaGetSymbolAddress((void**)&c16,   g_ctx16);
    cudaGetSymbolAddress((void**)&x16,   g_x16);
    cudaGetSymbolAddress((void**)&pre16, g_pre16);
    cudaGetSymbolAddress((void**)&v1t16, g_wv1t16);
    cudaGetSymbolAddress((void**)&wkt16, g_wkt16);
    cudaGetSymbolAddress((void**)&wqt16, g_wqt16);
    cudaGetSymbolAddress((void**)&wot16, g_woutt16);

    const int DYNSMEM = 1024 + 4 * STAGE_BYTES;   // 132096
    cudaFuncSetAttribute(mma_gemm<float>,  cudaFuncAttributeMaxDynamicSharedMemorySize, DYNSMEM);
    cudaFuncSetAttribute(mma_gemm<__half>, cudaFuncAttributeMaxDynamicSharedMemorySize, DYNSMEM);

    const int MSMALL = BB * NQ;                  // 256

    // 0) fp16 conversions
    const int n4c = BB * NCTX * DIMV / 4;
    const int n4x = BB * NQ * DIMV / 4;
    cvt_f16<<<(n4c + 255) / 256, 256>>>(ctx, c16, n4c);
    cvt_f16<<<(n4x + 255) / 256, 256>>>(x, x16, n4x);
    cvt_t_f16<<<dim3(QR / 32, DIMV / 32), dim3(32, 8)>>>(Wv1, v1t16, DIMV, QR);
    cvt_t_f16<<<dim3(DIMV / 32, DIMV / 32), dim3(32, 8)>>>(Wk, wkt16, DIMV, DIMV);
    cvt_t_f16<<<dim3(DIMV / 32, DIMV / 32), dim3(32, 8)>>>(Wq, wqt16, DIMV, DIMV);
    cvt_t_f16<<<dim3(DIMV / 32, DIMV / 32), dim3(32, 8)>>>(Wout, wot16, DIMV, DIMV);

    // 1) q = x @ Wq   (fp16 mma, fp32 out)
    mma_gemm<float><<<dim3(DIMV / 128, MSMALL / 128), 256, DYNSMEM>>>(
        x16, wqt16, q, MSMALL, DIMV, DIMV);
    // 2) k = ctx @ Wk
    mma_gemm<float><<<dim3(DIMV / 128, (BB * NCTX) / 128), 256, DYNSMEM>>>(
        c16, wkt16, k, BB * NCTX, DIMV, DIMV);
    // 3) h1 = ctx @ Wv1 (dominant; fp16 output)
    mma_gemm<__half><<<dim3(QR / 128, (BB * NCTX) / 128), 256, DYNSMEM>>>(
        c16, v1t16, h1h, BB * NCTX, QR, DIMV);
    // 4) LN stats (apply fused in accred)
    ln_stats<<<BB * NCTX, 256>>>(h1h, stats);
    // 5) attention scores
    sim_kernel<<<dim3(NCTX / 128, BB * NHD), 256>>>(q, k, attn);
    // 6) softmax
    softmax_kernel<<<BB * NHD * NQ, 256>>>(attn);
    // 7) acc = attn x LN(vmid)
    accred_kernel<<<BB * NQ, 256>>>(attn, h1h, stats, ln_g, ln_b, acc);
    // 8) pre16 = acc x Wc (fp16 out)
    mix_kernel<<<BB * NQ, 256>>>(acc, Wc, pre16);
    // 9) out = pre @ Wout (fp16 mma, fp32 out)
    mma_gemm<float><<<dim3(DIMV / 128, MSMALL / 128), 256, DYNSMEM>>>(
        pre16, wot16, out, MSMALL, DIMV, DIMV);
}

// round 17
// speedup vs baseline: 1.1486x; 1.1486x over previous
#include <cuda_runtime.h>
#include <cuda_fp16.h>
#include <cstdint>
#include <math.h>

// Problem constants
#define BB    4
#define NQ    64
#define NCTX  1024
#define DIMV  768
#define NHD   8
#define DH    96
#define RNK   64
#define QR    4096      // NQ*RNK

// Scratch (static device arrays — no allocation allowed)
__device__ float g_q    [BB*NQ*DIMV];
__device__ float g_k    [BB*NCTX*DIMV];
__device__ float g_h1   [BB*NCTX*QR];
__device__ float g_attn [BB*NHD*NQ*NCTX];
__device__ float g_accp [4*BB*NQ*NHD*RNK];    // 4-way j-split partials (2MB)
__device__ float g_pre  [BB*NQ*DIMV];
__device__ float g_stats[BB*NCTX*2];          // per-row LN mean/rstd
__device__ float g_part [6*BB*NQ*DIMV];       // split-K partials (6 x 256 x 768)
// fp16 operands for tensor-core GEMMs (single precision pass, calibrated err)
__device__ __half g_ctx16 [BB*NCTX*DIMV];
__device__ __half g_wv1t16[QR*DIMV];          // Wv1^T [N=4096, K=768]
__device__ __half g_wkt16 [DIMV*DIMV];        // Wk^T [768, 768]

// ===========================================================================
// PTX helpers (baseline PTX only — harness targets compute_103, no 'a' feats)
// ===========================================================================
__device__ __forceinline__ uint32_t smem_u32(const void* p) {
    uint32_t a;
    asm("{ .reg .u64 t; cvta.to.shared.u64 t, %1; cvt.u32.u64 %0, t; }"
        : "=r"(a) : "l"(p));
    return a;
}
__device__ __forceinline__ void cp16(uint32_t dst, const void* src) {
    asm volatile("cp.async.cg.shared.global [%0], [%1], 16;" :: "r"(dst), "l"(src));
}
__device__ __forceinline__ void ldm_x4(uint32_t* r, uint32_t addr) {
    asm volatile("ldmatrix.sync.aligned.m8n8.x4.shared.b16 {%0,%1,%2,%3}, [%4];"
                 : "=r"(r[0]), "=r"(r[1]), "=r"(r[2]), "=r"(r[3]) : "r"(addr));
}
__device__ __forceinline__ void mma16816h(float* c, const uint32_t* a, const uint32_t* b) {
    asm volatile(
        "mma.sync.aligned.m16n8k16.row.col.f32.f16.f16.f32 "
        "{%0,%1,%2,%3}, {%4,%5,%6,%7}, {%8,%9}, {%0,%1,%2,%3};"
        : "+f"(c[0]), "+f"(c[1]), "+f"(c[2]), "+f"(c[3])
        : "r"(a[0]), "r"(a[1]), "r"(a[2]), "r"(a[3]), "r"(b[0]), "r"(b[1]));
}

// ===========================================================================
// Single-pass fp16 GEMM via mma.sync: C[M,N](fp32) = A[M,K] @ B^T, B in [N,K].
// CTA tile 128x128, 8 warps (4 Mw x 2 Nw, 32x64 each), K-chunk 64,
// 4-stage cp.async pipeline (2 tiles x 16KB per stage), XOR-swizzled SMEM.
// ===========================================================================
#define STAGE_BYTES 32768
__global__ __launch_bounds__(256, 1)
void mma_gemm(const __half* __restrict__ A16, const __half* __restrict__ B16,
              float* __restrict__ C, int M, int N, int K) {
    extern __shared__ char smem_raw[];
    const uint32_t sb0 = smem_u32(smem_raw);
    const uint32_t sbase = (sb0 + 1023u) & ~1023u;     // 1KB-aligned tile area
    const int tid  = threadIdx.x;
    const int wid  = tid >> 5, lane = tid & 31;
    const int mw   = wid & 3, nw = wid >> 2;           // warp grid 4x2
    const int bm = blockIdx.y * 128, bn = blockIdx.x * 128;

    const __half* gsrc[2] = { A16 + (size_t)bm * K, B16 + (size_t)bn * K };

    const int ldrow = tid >> 3;           // 0..31  (x4 row groups of 32)
    const int ldq   = tid & 7;            // 16B column within 128B row
    uint32_t sdst[4];
    #pragma unroll
    for (int u = 0; u < 4; ++u) {
        uint32_t off = (uint32_t)((ldrow + u * 32) * 128 + ldq * 16);
        sdst[u] = off ^ ((off >> 3) & 0x70u);
    }

    auto issue_chunk = [&](int cc, uint32_t stb) {
        const int kc = cc << 6;
        #pragma unroll
        for (int a = 0; a < 2; ++a) {
            const __half* s = gsrc[a] + kc + ldq * 8;
            #pragma unroll
            for (int u = 0; u < 4; ++u)
                cp16(stb + a * 16384 + sdst[u], s + (size_t)(ldrow + u * 32) * K);
        }
    };

    uint32_t aOff[2], aPerm[2];
    #pragma unroll
    for (int mt = 0; mt < 2; ++mt) {
        int row = mw * 32 + mt * 16 + (lane & 15);
        aOff[mt]  = (uint32_t)(row * 128 + (lane >> 4) * 16);
        aPerm[mt] = (uint32_t)((row & 7) << 4);
    }
    const int nlb = nw * 64 + (lane & 7) + ((lane >> 4) << 3);
    const uint32_t bOff0 = (uint32_t)(nlb * 128 + ((lane >> 3) & 1) * 16);
    const uint32_t bPerm = (uint32_t)((nlb & 7) << 4);

    float acc[2][8][4];
    #pragma unroll
    for (int mt = 0; mt < 2; ++mt)
        #pragma unroll
        for (int nt = 0; nt < 8; ++nt)
            #pragma unroll
            for (int j = 0; j < 4; ++j) acc[mt][nt][j] = 0.f;

    const int nchunks = K >> 6;

    issue_chunk(0, sbase);
    asm volatile("cp.async.commit_group;");
    issue_chunk(1, sbase + STAGE_BYTES);
    asm volatile("cp.async.commit_group;");
    issue_chunk(2, sbase + 2 * STAGE_BYTES);
    asm volatile("cp.async.commit_group;");

    for (int c = 0; c < nchunks; ++c) {
        if (c + 3 < nchunks) {
            issue_chunk(c + 3, sbase + (uint32_t)((c + 3) & 3) * STAGE_BYTES);
            asm volatile("cp.async.commit_group;");
            asm volatile("cp.async.wait_group 3;");
        } else if (c + 2 < nchunks) {
            asm volatile("cp.async.wait_group 2;");
        } else if (c + 1 < nchunks) {
            asm volatile("cp.async.wait_group 1;");
        } else {
            asm volatile("cp.async.wait_group 0;");
        }
        __syncthreads();

        const uint32_t stb = sbase + (uint32_t)(c & 3) * STAGE_BYTES;
        const uint32_t aB = stb, bB = stb + 16384;

        #pragma unroll
        for (int ks = 0; ks < 4; ++ks) {
            const uint32_t k32 = (uint32_t)(ks * 32);
            uint32_t a16[2][4];
            #pragma unroll
            for (int mt = 0; mt < 2; ++mt)
                ldm_x4(a16[mt], aB + ((aOff[mt] + k32) ^ aPerm[mt]));
            #pragma unroll
            for (int np = 0; np < 4; ++np) {
                uint32_t bfr[4];
                const uint32_t bo = bOff0 + (uint32_t)(np * 2048) + k32;
                ldm_x4(bfr, bB + (bo ^ bPerm));
                #pragma unroll
                for (int mt = 0; mt < 2; ++mt) {
                    mma16816h(acc[mt][np * 2],     a16[mt], bfr);
                    mma16816h(acc[mt][np * 2 + 1], a16[mt], bfr + 2);
                }
            }
        }
        __syncthreads();
    }

    const int r0 = bm + mw * 32 + (lane >> 2);
    const int c0 = bn + nw * 64 + (lane & 3) * 2;
    #pragma unroll
    for (int mt = 0; mt < 2; ++mt) {
        #pragma unroll
        for (int nt = 0; nt < 8; ++nt) {
            float* p0 = C + (size_t)(r0 + mt * 16) * N + c0 + nt * 8;
            float* p1 = p0 + (size_t)8 * N;
            *(float2*)p0 = make_float2(acc[mt][nt][0], acc[mt][nt][1]);
            *(float2*)p1 = make_float2(acc[mt][nt][2], acc[mt][nt][3]);
        }
    }
}

// ===========================================================================
// fp32 -> fp16 (same layout)
// ===========================================================================
__global__ __launch_bounds__(256) void cvt_f16(const float* __restrict__ x,
                                               __half* __restrict__ y, int n4) {
    int i = blockIdx.x * 256 + threadIdx.x;
    if (i >= n4) return;
    float4 v = ((const float4*)x)[i];
    ((__half2*)y)[i * 2]     = __floats2half2_rn(v.x, v.y);
    ((__half2*)y)[i * 2 + 1] = __floats2half2_rn(v.z, v.w);
}

// W[K,N] fp32 -> W^T fp16 [N,K]
__global__ void cvt_t_f16(const float* __restrict__ W,
                          __half* __restrict__ T, int K, int N) {
    __shared__ float t[32][33];
    const int n0 = blockIdx.x * 32, k0 = blockIdx.y * 32;
    const int tx = threadIdx.x, ty = threadIdx.y;   // 32 x 8
    #pragma unroll
    for (int u = 0; u < 4; ++u) {
        int r = ty + u * 8;
        t[r][tx] = W[(size_t)(k0 + r) * N + n0 + tx];
    }
    __syncthreads();
    #pragma unroll
    for (int u = 0; u < 4; ++u) {
        int r = ty + u * 8;               // local n
        T[(size_t)(n0 + r) * K + k0 + tx] = __float2half_rn(t[tx][r]);
    }
}

// ===========================================================================
// Split-K fp32 SGEMM, tile 64x64, S-way K split -> partials; then reduce6.
// ===========================================================================
__global__ __launch_bounds__(256) void sgemm_sk(const float* __restrict__ A,
                                                const float* __restrict__ Bm,
                                                float* __restrict__ part,
                                                int M, int N, int K, int klen) {
    __shared__ float As[16][64];
    __shared__ float Bs[16][64];
    const int bm = blockIdx.y * 64, bn = blockIdx.x * 64;
    const int z  = blockIdx.z;
    const int tid = threadIdx.x;
    const int arow = tid >> 2, acol = (tid & 3) * 4;
    const int brow = tid >> 4, bcol = (tid & 15) * 4;
    const int tx = tid & 15, ty = tid >> 4;

    float acc[4][4] = {};
    const float* Ap = A + (size_t)(bm + arow) * K + z * klen + acol;
    const float* Bp = Bm + (size_t)(z * klen + brow) * N + bn + bcol;

    float4 a_reg = *(const float4*)(Ap);
    float4 b_reg = *(const float4*)(Bp);

    for (int kt = 0; kt < klen; kt += 16) {
        As[acol + 0][arow] = a_reg.x;
        As[acol + 1][arow] = a_reg.y;
        As[acol + 2][arow] = a_reg.z;
        As[acol + 3][arow] = a_reg.w;
        *(float4*)&Bs[brow][bcol] = b_reg;
        __syncthreads();

        if (kt + 16 < klen) {
            a_reg = *(const float4*)(Ap + kt + 16);
            b_reg = *(const float4*)(Bp + (size_t)(kt + 16) * N);
        }

        #pragma unroll
        for (int k = 0; k < 16; ++k) {
            float4 a = *(float4*)&As[k][ty * 4];
            float4 b = *(float4*)&Bs[k][tx * 4];
            float af[4] = {a.x, a.y, a.z, a.w};
            float bf[4] = {b.x, b.y, b.z, b.w};
            #pragma unroll
            for (int i = 0; i < 4; ++i)
                #pragma unroll
                for (int j = 0; j < 4; ++j)
                    acc[i][j] += af[i] * bf[j];
        }
        __syncthreads();
    }

    float* P = part + (size_t)z * M * N;
    #pragma unroll
    for (int i = 0; i < 4; ++i) {
        float4 c = {acc[i][0], acc[i][1], acc[i][2], acc[i][3]};
        *(float4*)(P + (size_t)(bm + ty * 4 + i) * N + bn + tx * 4) = c;
    }
}

__global__ __launch_bounds__(256) void reduce6(const float* __restrict__ part,
                                               float* __restrict__ out, int mn) {
    int i = blockIdx.x * 256 + threadIdx.x;
    if (i >= mn / 4) return;
    float4 r = make_float4(0.f, 0.f, 0.f, 0.f);
    #pragma unroll
    for (int s = 0; s < 6; ++s) {
        float4 v = ((const float4*)(part + (size_t)s * mn))[i];
        r.x += v.x; r.y += v.y; r.z += v.z; r.w += v.w;
    }
    ((float4*)out)[i] = r;
}

// ===========================================================================
// LN statistics only: per row of h1 (4096 wide) -> (mean, rstd)
// ===========================================================================
__global__ __launch_bounds__(256) void ln_stats(const float* __restrict__ h1,
                                                float* __restrict__ stats) {
    __shared__ float r1[8], r2[8];
    const int row = blockIdx.x;
    const float* p = h1 + (size_t)row * QR;
    const int tid = threadIdx.x, lane = tid & 31, wid = tid >> 5;

    float s = 0.f, ss = 0.f;
    #pragma unroll
    for (int u = 0; u < 4; ++u) {
        float4 v = *(const float4*)(p + tid * 4 + u * 1024);
        s  += v.x + v.y + v.z + v.w;
        ss += v.x * v.x + v.y * v.y + v.z * v.z + v.w * v.w;
    }
    #pragma unroll
    for (int o = 16; o; o >>= 1) {
        s  += __shfl_xor_sync(0xffffffffu, s, o);
        ss += __shfl_xor_sync(0xffffffffu, ss, o);
    }
    if (lane == 0) { r1[wid] = s; r2[wid] = ss; }
    __syncthreads();
    if (tid == 0) {
        s = 0.f; ss = 0.f;
        #pragma unroll
        for (int w = 0; w < 8; ++w) { s += r1[w]; ss += r2[w]; }
        const float mean = s * (1.f / 4096.f);
        const float var  = ss * (1.f / 4096.f) - mean * mean;
        stats[row * 2]     = mean;
        stats[row * 2 + 1] = rsqrtf(var + 1e-5f);
    }
}

// ===========================================================================
// sim[b,h,i,j] = (1/sqrt(dh)) * q[b,i,h*96:] . k[b,j,h*96:]
// ===========================================================================
__global__ __launch_bounds__(256) void sim_kernel(const float* __restrict__ q,
                                                  const float* __restrict__ k,
                                                  float* __restrict__ attn) {
    __shared__ float Qs[96][64];
    __shared__ float Ks[32][128];
    const int bh = blockIdx.y;
    const int b = bh >> 3, h = bh & 7;
    const int j0 = blockIdx.x * 128;
    const int tid = threadIdx.x;

    #pragma unroll
    for (int u = 0; u < 6; ++u) {
        int lin = tid + u * 256;
        int i = lin / 24, c4 = lin % 24;
        float4 v = *(const float4*)(q + (size_t)(b * NQ + i) * DIMV + h * DH + c4 * 4);
        Qs[c4 * 4 + 0][i] = v.x;
        Qs[c4 * 4 + 1][i] = v.y;
        Qs[c4 * 4 + 2][i] = v.z;
        Qs[c4 * 4 + 3][i] = v.w;
    }

    const int tx = tid & 15, ty = tid >> 4;
    float acc[4][8] = {};

    for (int kc = 0; kc < 96; kc += 32) {
        __syncthreads();
        #pragma unroll
        for (int u = 0; u < 4; ++u) {
            int lin = tid + u * 256;
            int j = lin >> 3, c4 = lin & 7;
            float4 v = *(const float4*)(k + (size_t)(b * NCTX + j0 + j) * DIMV + h * DH + kc + c4 * 4);
            Ks[c4 * 4 + 0][j] = v.x;
            Ks[c4 * 4 + 1][j] = v.y;
            Ks[c4 * 4 + 2][j] = v.z;
            Ks[c4 * 4 + 3][j] = v.w;
        }
        __syncthreads();
        #pragma unroll
        for (int kk = 0; kk < 32; ++kk) {
            float4 a = *(float4*)&Qs[kc + kk][ty * 4];
            float4 b0 = *(float4*)&Ks[kk][tx * 8];
            float4 b1 = *(float4*)&Ks[kk][tx * 8 + 4];
            float af[4] = {a.x, a.y, a.z, a.w};
            float bf[8] = {b0.x, b0.y, b0.z, b0.w, b1.x, b1.y, b1.z, b1.w};
            #pragma unroll
            for (int i = 0; i < 4; ++i)
                #pragma unroll
                for (int j = 0; j < 8; ++j)
                    acc[i][j] += af[i] * bf[j];
        }
    }

    const float scale = 0.10206207261596576f;  // 1/sqrt(96)
    #pragma unroll
    for (int i = 0; i < 4; ++i) {
        size_t base = (size_t)((b * NHD + h) * NQ + ty * 4 + i) * NCTX + j0 + tx * 8;
        float4 o0 = {acc[i][0] * scale, acc[i][1] * scale, acc[i][2] * scale, acc[i][3] * scale};
        float4 o1 = {acc[i][4] * scale, acc[i][5] * scale, acc[i][6] * scale, acc[i][7] * scale};
        *(float4*)(attn + base) = o0;
        *(float4*)(attn + base + 4) = o1;
    }
}

// ===========================================================================
// Softmax over last dim (1024) of attn, in place.
// ===========================================================================
__global__ __launch_bounds__(256) void softmax_kernel(float* __restrict__ attn) {
    __shared__ float red[8];
    const int row = blockIdx.x;
    float* p = attn + (size_t)row * NCTX;
    const int tid = threadIdx.x, lane = tid & 31, wid = tid >> 5;

    float4 v = *(float4*)(p + tid * 4);
    float m = fmaxf(fmaxf(v.x, v.y), fmaxf(v.z, v.w));
    #pragma unroll
    for (int o = 16; o; o >>= 1) m = fmaxf(m, __shfl_xor_sync(0xffffffffu, m, o));
    if (lane == 0) red[wid] = m;
    __syncthreads();
    m = red[0];
    #pragma unroll
    for (int w = 1; w < 8; ++w) m = fmaxf(m, red[w]);

    v.x = __expf(v.x - m);
    v.y = __expf(v.y - m);
    v.z = __expf(v.z - m);
    v.w = __expf(v.w - m);
    float s = v.x + v.y + v.z + v.w;
    #pragma unroll
    for (int o = 16; o; o >>= 1) s += __shfl_xor_sync(0xffffffffu, s, o);
    __syncthreads();
    if (lane == 0) red[wid] = s;
    __syncthreads();
    s = 0.f;
    #pragma unroll
    for (int w = 0; w < 8; ++w) s += red[w];
    const float inv = 1.f / s;
    v.x *= inv; v.y *= inv; v.z *= inv; v.w *= inv;
    *(float4*)(p + tid * 4) = v;
}

// ===========================================================================
// Split-j accred: partial[jz][b,i,h,r] = sum_{j in jz-range} attn * LN(h1)
// grid (BB*NQ, 4); each CTA covers 256 j (4 tiles of 64). Deterministic:
// fixed j-ranges, fixed reduction order in mix_kernel.
// ===========================================================================
#define ACC_SEG (BB*NQ*NHD*RNK)
__global__ __launch_bounds__(256) void accred_kernel(const float* __restrict__ attn,
                                                     const float* __restrict__ h1,
                                                     const float* __restrict__ stats,
                                                     const float* __restrict__ ln_g,
                                                     const float* __restrict__ ln_b,
                                                     float* __restrict__ accp) {
    __shared__ float vs[64][64];
    __shared__ float as_[8][64];
    __shared__ float gsh[64], bsh[64];
    const int bi = blockIdx.x;
    const int jz = blockIdx.y;
    const int b = bi >> 6, i = bi & 63;
    const int tid = threadIdx.x;
    const int h = tid >> 5, lane = tid & 31;

    if (tid < 64) {
        gsh[tid] = ln_g[i * RNK + tid];
        bsh[tid] = ln_b[i * RNK + tid];
    }

    float acc0 = 0.f, acc1 = 0.f;

    const int j_lo = jz * 256, j_hi = j_lo + 256;
    for (int jt = j_lo; jt < j_hi; jt += 64) {
        __syncthreads();
        {
            int e = tid * 2;
            int he = e >> 6, je = e & 63;
            float2 v = *(const float2*)(attn + (size_t)((b * NHD + he) * NQ + i) * NCTX + jt + je);
            as_[he][je] = v.x;
            as_[he][je + 1] = v.y;
        }
        {
            int rrow = tid >> 2;
            int cbase = (tid & 3) * 16;
            const int grow = b * NCTX + jt + rrow;
            const float2 st = *(const float2*)(stats + grow * 2);
            const float mu = st.x, rs = st.y;
            const float* src = h1 + (size_t)grow * QR + i * RNK + cbase;
            #pragma unroll
            for (int v4 = 0; v4 < 4; ++v4) {
                float4 v = *(const float4*)(src + v4 * 4);
                const int cb = cbase + v4 * 4;
                v.x = (v.x - mu) * rs * gsh[cb + 0] + bsh[cb + 0];
                v.y = (v.y - mu) * rs * gsh[cb + 1] + bsh[cb + 1];
                v.z = (v.z - mu) * rs * gsh[cb + 2] + bsh[cb + 2];
                v.w = (v.w - mu) * rs * gsh[cb + 3] + bsh[cb + 3];
                *(float4*)&vs[rrow][cb] = v;
            }
        }
        __syncthreads();
        #pragma unroll 8
        for (int j = 0; j < 64; ++j) {
            float a = as_[h][j];
            acc0 += a * vs[j][lane];
            acc1 += a * vs[j][lane + 32];
        }
    }
    size_t base = (size_t)jz * ACC_SEG + (size_t)((b * NQ + i) * NHD + h) * RNK;
    accp[base + lane] = acc0;
    accp[base + lane + 32] = acc1;
}

// ===========================================================================
// pre[b,i,d] = sum_r (sum_jz accp[jz][b,i,h(d),r]) * Wc[i,r,d]
// ===========================================================================
__global__ __launch_bounds__(256) void mix_kernel(const float* __restrict__ accp,
                                                  const float* __restrict__ Wc,
                                                  float* __restrict__ pre) {
    __shared__ float as_[8][64];
    const int bi = blockIdx.x;
    const int b = bi >> 6, i = bi & 63;
    const int tid = threadIdx.x;

    {
        const size_t off = (size_t)(b * NQ + i) * NHD * RNK;
        float2 s0 = ((const float2*)(accp + off))[tid];
        float2 s1 = ((const float2*)(accp + ACC_SEG + off))[tid];
        float2 s2 = ((const float2*)(accp + 2 * (size_t)ACC_SEG + off))[tid];
        float2 s3 = ((const float2*)(accp + 3 * (size_t)ACC_SEG + off))[tid];
        ((float2*)&as_[0][0])[tid] = make_float2(s0.x + s1.x + s2.x + s3.x,
                                                 s0.y + s1.y + s2.y + s3.y);
    }
    __syncthreads();

    #pragma unroll
    for (int u = 0; u < 3; ++u) {
        const int d = tid + u * 256;
        const int h = d / DH;
        const float* w = Wc + (size_t)i * RNK * DIMV + d;
        float s = 0.f;
        #pragma unroll 8
        for (int r = 0; r < 64; ++r) s += as_[h][r] * w[(size_t)r * DIMV];
        pre[(size_t)(b * NQ + i) * DIMV + d] = s;
    }
}

// ===========================================================================
// Launch
// ===========================================================================
extern "C" void kernel_launch(void* const* d_in, const int* in_sizes, int n_in,
                              void* d_out, int out_size) {
    const float* x    = (const float*)d_in[0];
    const float* ctx  = (const float*)d_in[1];
    const float* Wq   = (const float*)d_in[2];
    const float* Wk   = (const float*)d_in[3];
    const float* Wv1  = (const float*)d_in[4];
    const float* ln_g = (const float*)d_in[5];
    const float* ln_b = (const float*)d_in[6];
    const float* Wc   = (const float*)d_in[7];
    const float* Wout = (const float*)d_in[8];
    float* out = (float*)d_out;

    float *q, *k, *h1, *attn, *accp, *pre, *stats, *part;
    __half *c16, *v1t16, *wkt16;
    cudaGetSymbolAddress((void**)&q,     g_q);
    cudaGetSymbolAddress((void**)&k,     g_k);
    cudaGetSymbolAddress((void**)&h1,    g_h1);
    cudaGetSymbolAddress((void**)&attn,  g_attn);
    cudaGetSymbolAddress((void**)&accp,  g_accp);
    cudaGetSymbolAddress((void**)&pre,   g_pre);
    cudaGetSymbolAddress((void**)&stats, g_stats);
    cudaGetSymbolAddress((void**)&part,  g_part);
    cudaGetSymbolAddress((void**)&c16,   g_ctx16);
    cudaGetSymbolAddress((void**)&v1t16, g_wv1t16);
    cudaGetSymbolAddress((void**)&wkt16, g_wkt16);

    const int DYNSMEM = 1024 + 4 * STAGE_BYTES;   // 1KB pad + 4 stages x 32KB = 132096
    cudaFuncSetAttribute(mma_gemm, cudaFuncAttributeMaxDynamicSharedMemorySize, DYNSMEM);

    const int MSMALL = BB * NQ;                  // 256
    const int MN     = MSMALL * DIMV;            // 196608
    const int SPLITK = 6, KLEN = DIMV / SPLITK;  // 128

    // 0) fp16 conversions
    const int n4 = BB * NCTX * DIMV / 4;
    cvt_f16<<<(n4 + 255) / 256, 256>>>(ctx, c16, n4);
    cvt_t_f16<<<dim3(QR / 32, DIMV / 32), dim3(32, 8)>>>(Wv1, v1t16, DIMV, QR);
    cvt_t_f16<<<dim3(DIMV / 32, DIMV / 32), dim3(32, 8)>>>(Wk, wkt16, DIMV, DIMV);

    // 1) q = x @ Wq   (split-K fp32, 288 CTAs)
    sgemm_sk<<<dim3(DIMV / 64, MSMALL / 64, SPLITK), 256>>>(x, Wq, part, MSMALL, DIMV, DIMV, KLEN);
    reduce6<<<(MN / 4 + 255) / 256, 256>>>(part, q, MN);
    // 2) k = ctx @ Wk  (single-pass fp16 tensor cores)
    mma_gemm<<<dim3(DIMV / 128, (BB * NCTX) / 128), 256, DYNSMEM>>>(
        c16, wkt16, k, BB * NCTX, DIMV, DIMV);
    // 3) h1 = ctx @ Wv1 (dominant, single-pass fp16 tensor cores)
    mma_gemm<<<dim3(QR / 128, (BB * NCTX) / 128), 256, DYNSMEM>>>(
        c16, v1t16, h1, BB * NCTX, QR, DIMV);
    // 4) LN stats only (apply fused in accred)
    ln_stats<<<BB * NCTX, 256>>>(h1, stats);
    // 5) attention scores
    sim_kernel<<<dim3(NCTX / 128, BB * NHD), 256>>>(q, k, attn);
    // 6) softmax
    softmax_kernel<<<BB * NHD * NQ, 256>>>(attn);
    // 7) accred split-j (4-way, deterministic partials)
    accred_kernel<<<dim3(BB * NQ, 4), 256>>>(attn, h1, stats, ln_g, ln_b, accp);
    // 8) pre = (sum partials) x Wc
    mix_kernel<<<BB * NQ, 256>>>(accp, Wc, pre);
    // 9) out = pre @ Wout (split-K fp32)
    sgemm_sk<<<dim3(DIMV / 64, MSMALL / 64, SPLITK), 256>>>(pre, Wout, part, MSMALL, DIMV, DIMV, KLEN);
    reduce6<<<(MN / 4 + 255) / 256, 256>>>(part, out, MN);
}